// round 16
// baseline (speedup 1.0000x reference)
#include <cuda_runtime.h>
#include <mma.h>
using namespace nvcuda;

// Problem constants
#define BATCH   4
#define SEQLEN  65536
#define RC      32
#define OC      256
#define NBLOCKS 2
#define NLAYERS 10

#define TL      128
#define FGLD    132
#define WALD    40
#define SM_FIXED (64 * FGLD + 3 * 64 * WALD + 128)

// ---- fused-5 kernel geometry ----
#define F5TL    256
#define F5NT    18
#define RS2     316
#define F5LD    292
#define SLD     260
#define SM_F5   (2*32*RS2 + 64*F5LD + 32*SLD + 3*64*WALD + 128)

// ---- head geometry: HC=64, 2 CTAs/SM ----
#define HC      64
#define HLDH    68
#define WCHK    8
#define WCLD    12
#define SM_HEAD (264 * HLDH + 40 * HLDH + 2 * 256 * WCLD)

// -------- scratch (device globals) --------
__device__ float g_resid[2][BATCH * RC * SEQLEN];
__device__ float g_skip[BATCH * RC * SEQLEN];
__device__ float g_w1e[OC * 40];
__device__ float g_w2e[OC * 264];

// ----------------------------------------------------------------
__global__ void k_prepw(const float* __restrict__ w1, const float* __restrict__ b1,
                        const float* __restrict__ w2, const float* __restrict__ b2)
{
    int idx = blockIdx.x * blockDim.x + threadIdx.x;
    const int N2 = OC * 264;
    if (idx < N2) {
        int m = idx / 264, c = idx % 264;
        float v = (c < 256) ? w2[(size_t)m * 256 + c] : (c == 256 ? b2[m] : 0.f);
        g_w2e[idx] = wmma::__float_to_tf32(v);
    } else if (idx < N2 + OC * 40) {
        int j = idx - N2;
        int m = j / 40, c = j % 40;
        float v = (c < 32) ? w1[(size_t)m * 32 + c] : (c == 32 ? b1[m] : 0.f);
        g_w1e[j] = wmma::__float_to_tf32(v);
    }
}

// Fragment row-half selector: element t sits at row (lane>>2) + 8*((t>>1)&1).
#define FRAG_HALF(t) (((t) >> 1) & 1)

// ----------------------------------------------------------------
// Fused first-5 layers of one block (identical to R15).
// ----------------------------------------------------------------
__global__ __launch_bounds__(512, 1)
void k_fuse5(int pingIn, int blk0, int liBase,
             const float* __restrict__ fwB, const float* __restrict__ fbB,
             const float* __restrict__ gwB, const float* __restrict__ gbB,
             const float* __restrict__ rwB, const float* __restrict__ rbB,
             const float* __restrict__ swB, const float* __restrict__ sbB,
             const float* __restrict__ x,
             const float* __restrict__ wst, const float* __restrict__ bst)
{
    extern __shared__ float smem[];
    float* Rb   = smem;                       // [2][32][RS2]
    float* u    = Rb + 2 * 32 * RS2;          // [64][F5LD]
    float* S    = u + 64 * F5LD;              // [32][SLD]
    float* wA   = S + 32 * SLD;               // [3][64][WALD]
    float* bias = wA + 3 * 64 * WALD;         // [128]

    int tid = threadIdx.x;
    int b = blockIdx.y;
    int l0 = blockIdx.x * F5TL;

    const float* __restrict__ rin = &g_resid[pingIn][(size_t)b * RC * SEQLEN];
    float* __restrict__ rout = &g_resid[pingIn ^ 1][(size_t)b * RC * SEQLEN];
    float* __restrict__ sk = &g_skip[(size_t)b * RC * SEQLEN];

    {
        const float* __restrict__ xb = &x[(size_t)b * SEQLEN];
        for (int i = tid; i < 32 * 72; i += 512) {
            int row = i / 72;
            int col = 16 + (i - row * 72) * 4;
            int l = l0 - 32 + col;
            float4 v = make_float4(0.f, 0.f, 0.f, 0.f);
            if (l >= 0 && l < SEQLEN) {
                if (blk0) {
                    float4 xv = *(const float4*)&xb[l];
                    float wv = wst[row], bv = bst[row];
                    v = make_float4(wv * xv.x + bv, wv * xv.y + bv,
                                    wv * xv.z + bv, wv * xv.w + bv);
                } else {
                    v = *(const float4*)&rin[(size_t)row * SEQLEN + l];
                }
            }
            *(float4*)&Rb[row * RS2 + col] = v;
        }
    }
    for (int i = tid; i < 32 * 64; i += 512) {
        int row = i >> 6;
        int n = (i & 63) * 4;
        float4 v = make_float4(0.f, 0.f, 0.f, 0.f);
        if (!blk0)
            v = *(const float4*)&sk[(size_t)row * SEQLEN + l0 + n];
        *(float4*)&S[row * SLD + n] = v;
    }

    int warp = tid >> 5;
    int lane = tid & 31;
    int grp = lane >> 2;

    int cur = 0;
    for (int j = 0; j < 5; j++) {
        int li = liBase + j;
        int offA, offB;
        if (j == 0) { offA = -1; offB = 0; }
        else { int h = 1 << (j - 1); offA = -h; offB = h; }

        const float2* fw2 = (const float2*)(fwB + (size_t)li * RC * RC * 2);
        const float2* gw2 = (const float2*)(gwB + (size_t)li * RC * RC * 2);
        const float* rw = rwB + (size_t)li * RC * RC;
        const float* sw = swB + (size_t)li * RC * RC;
        for (int i = tid; i < 64 * 32; i += 512) {
            int row = i >> 5, ci = i & 31;
            int c = row & 31;
            float t0, t1, t2;
            if (row < 32) {
                float2 t = fw2[c * 32 + ci];
                t0 = t.x; t1 = t.y; t2 = rw[c * 32 + ci];
            } else {
                float2 t = gw2[c * 32 + ci];
                t0 = t.x; t1 = t.y; t2 = sw[c * 32 + ci];
            }
            wA[0 * 64 * WALD + row * WALD + ci] = wmma::__float_to_tf32(t0);
            wA[1 * 64 * WALD + row * WALD + ci] = wmma::__float_to_tf32(t1);
            wA[2 * 64 * WALD + row * WALD + ci] = wmma::__float_to_tf32(t2);
        }
        if (tid < 32) {
            bias[tid]      = fbB[li * RC + tid];
            bias[32 + tid] = gbB[li * RC + tid];
            bias[64 + tid] = rbB[li * RC + tid];
            bias[96 + tid] = sbB[li * RC + tid];
        }
        __syncthreads();

        const float* Rc = Rb + cur * 32 * RS2;
        float* Rn = Rb + (cur ^ 1) * 32 * RS2;

        for (int tt = 0; tt < 2; tt++) {
            int t = warp + tt * 16;
            if (t >= F5NT) break;
            int n0 = t * 16;

            wmma::fragment<wmma::accumulator, 16, 16, 8, float> acc[4];
#pragma unroll
            for (int mi = 0; mi < 4; mi++) wmma::fill_fragment(acc[mi], 0.f);
#pragma unroll
            for (int tap = 0; tap < 2; tap++) {
                const float* wAt = wA + tap * 64 * WALD;
                int bcol = 16 + n0 + (tap ? offB : offA);
#pragma unroll
                for (int kf = 0; kf < 4; kf++) {
                    wmma::fragment<wmma::matrix_a, 16, 16, 8, wmma::precision::tf32, wmma::row_major> a;
                    wmma::fragment<wmma::matrix_b, 16, 16, 8, wmma::precision::tf32, wmma::row_major> bf;
                    wmma::load_matrix_sync(bf, &Rc[(kf * 8) * RS2 + bcol], RS2);
#pragma unroll
                    for (int q = 0; q < bf.num_elements; q++)
                        bf.x[q] = wmma::__float_to_tf32(bf.x[q]);
#pragma unroll
                    for (int mi = 0; mi < 4; mi++) {
                        wmma::load_matrix_sync(a, &wAt[(mi * 16) * WALD + kf * 8], WALD);
                        wmma::mma_sync(acc[mi], a, bf, acc[mi]);
                    }
                }
            }
#pragma unroll
            for (int mi = 0; mi < 2; mi++) {
                float bf0 = bias[mi * 16 + grp];
                float bf1 = bias[mi * 16 + grp + 8];
                float bg0 = bias[32 + mi * 16 + grp];
                float bg1 = bias[32 + mi * 16 + grp + 8];
#pragma unroll
                for (int q = 0; q < 8; q++) {
                    float fv = acc[mi].x[q] + (FRAG_HALF(q) ? bf1 : bf0);
                    float gv = acc[mi + 2].x[q] + (FRAG_HALF(q) ? bg1 : bg0);
                    acc[mi].x[q] = wmma::__float_to_tf32(fv * gv);
                }
                wmma::store_matrix_sync(&u[(mi * 16) * F5LD + n0], acc[mi], F5LD, wmma::mem_row_major);
            }
            __syncwarp();

#pragma unroll
            for (int mi = 0; mi < 4; mi++) wmma::fill_fragment(acc[mi], 0.f);
            {
                const float* wA2 = wA + 2 * 64 * WALD;
#pragma unroll
                for (int kf = 0; kf < 4; kf++) {
                    wmma::fragment<wmma::matrix_b, 16, 16, 8, wmma::precision::tf32, wmma::row_major> bf;
                    wmma::load_matrix_sync(bf, &u[(kf * 8) * F5LD + n0], F5LD);
#pragma unroll
                    for (int mi = 0; mi < 4; mi++) {
                        wmma::fragment<wmma::matrix_a, 16, 16, 8, wmma::precision::tf32, wmma::row_major> a;
                        wmma::load_matrix_sync(a, &wA2[(mi * 16) * WALD + kf * 8], WALD);
                        wmma::mma_sync(acc[mi], a, bf, acc[mi]);
                    }
                }
            }
#pragma unroll
            for (int mi = 0; mi < 4; mi++) {
                int base = (mi < 2) ? (64 + mi * 16) : (96 + (mi - 2) * 16);
                float b0 = bias[base + grp];
                float b1 = bias[base + grp + 8];
#pragma unroll
                for (int q = 0; q < 8; q++)
                    acc[mi].x[q] += FRAG_HALF(q) ? b1 : b0;
                wmma::store_matrix_sync(&u[(mi * 16) * F5LD + n0], acc[mi], F5LD, wmma::mem_row_major);
            }
            __syncwarp();

            {
                int col4 = n0 + (lane & 3) * 4;
                int cb4 = (lane >> 2) * 4;
                int lb = l0 - 16 + col4;
                bool inS = (col4 >= 16 && col4 < 272);
#pragma unroll
                for (int cc = 0; cc < 4; cc++) {
                    int c = cb4 + cc;
                    float4 ur = *(const float4*)&u[c * F5LD + col4];
                    float4 rc = *(const float4*)&Rc[c * RS2 + 16 + col4];
                    float4 rv;
                    rv.x = (lb + 0 >= 0 && lb + 0 < SEQLEN) ? rc.x + ur.x : 0.f;
                    rv.y = (lb + 1 >= 0 && lb + 1 < SEQLEN) ? rc.y + ur.y : 0.f;
                    rv.z = (lb + 2 >= 0 && lb + 2 < SEQLEN) ? rc.z + ur.z : 0.f;
                    rv.w = (lb + 3 >= 0 && lb + 3 < SEQLEN) ? rc.w + ur.w : 0.f;
                    *(float4*)&Rn[c * RS2 + 16 + col4] = rv;
                    if (inS) {
                        float4 us = *(const float4*)&u[(32 + c) * F5LD + col4];
                        float4 sv = *(const float4*)&S[c * SLD + col4 - 16];
                        sv.x += us.x; sv.y += us.y; sv.z += us.z; sv.w += us.w;
                        *(float4*)&S[c * SLD + col4 - 16] = sv;
                    }
                }
            }
            __syncwarp();
        }
        __syncthreads();
        cur ^= 1;
    }

    const float* Rf = Rb + cur * 32 * RS2;
    for (int i = tid; i < 32 * 64; i += 512) {
        int row = i >> 6;
        int n = (i & 63) * 4;
        *(float4*)&rout[(size_t)row * SEQLEN + l0 + n] = *(const float4*)&Rf[row * RS2 + 32 + n];
        *(float4*)&sk[(size_t)row * SEQLEN + l0 + n] = *(const float4*)&S[row * SLD + n];
    }
}

// ----------------------------------------------------------------
// Single gated dilated layer (identical to R15).
// ----------------------------------------------------------------
__global__ __launch_bounds__(256, 2)
void k_layer_tc(int ping,
                const float* __restrict__ fw, const float* __restrict__ fb,
                const float* __restrict__ gw, const float* __restrict__ gb,
                const float* __restrict__ rw, const float* __restrict__ rb,
                const float* __restrict__ sw, const float* __restrict__ sb,
                int offA, int offB, int PAD, int HS)
{
    extern __shared__ float smem[];
    float* halo = smem;
    float* u    = smem + 32 * HS;
    float* wA   = u + 64 * FGLD;
    float* bias = wA + 3 * 64 * WALD;

    int tid = threadIdx.x;
    int b = blockIdx.y;
    int l0 = blockIdx.x * TL;

    const float* __restrict__ rin = &g_resid[ping][(size_t)b * RC * SEQLEN];
    float* __restrict__ rout = &g_resid[ping ^ 1][(size_t)b * RC * SEQLEN];
    float* __restrict__ sk = &g_skip[(size_t)b * RC * SEQLEN];

    const float2* fw2 = (const float2*)fw;
    const float2* gw2 = (const float2*)gw;
    for (int i = tid; i < 64 * 32; i += 256) {
        int row = i >> 5, ci = i & 31;
        int c = row & 31;
        float t0, t1, t2;
        if (row < 32) {
            float2 t = fw2[c * 32 + ci];
            t0 = t.x; t1 = t.y; t2 = rw[c * 32 + ci];
        } else {
            float2 t = gw2[c * 32 + ci];
            t0 = t.x; t1 = t.y; t2 = sw[c * 32 + ci];
        }
        wA[0 * 64 * WALD + row * WALD + ci] = wmma::__float_to_tf32(t0);
        wA[1 * 64 * WALD + row * WALD + ci] = wmma::__float_to_tf32(t1);
        wA[2 * 64 * WALD + row * WALD + ci] = wmma::__float_to_tf32(t2);
    }
    if (tid < 32) {
        bias[tid]      = fb[tid];
        bias[32 + tid] = gb[tid];
        bias[64 + tid] = rb[tid];
        bias[96 + tid] = sb[tid];
    }

    {
        int c0 = (PAD + offA) & ~3;
        int c1 = (PAD + TL + offB + 4) & ~3;
        int w4 = (c1 - c0) >> 2;
        for (int i = tid; i < 32 * w4; i += 256) {
            int row = i / w4;
            int col = c0 + ((i - row * w4) << 2);
            int l = l0 - PAD + col;
            float4 v = make_float4(0.f, 0.f, 0.f, 0.f);
            if (l >= 0 && l < SEQLEN)
                v = *(const float4*)&rin[(size_t)row * SEQLEN + l];
            v.x = wmma::__float_to_tf32(v.x);
            v.y = wmma::__float_to_tf32(v.y);
            v.z = wmma::__float_to_tf32(v.z);
            v.w = wmma::__float_to_tf32(v.w);
            *(float4*)&halo[row * HS + col] = v;
        }
    }
    __syncthreads();

    int warp = tid >> 5;
    int lane = tid & 31;
    int grp = lane >> 2;
    int n0 = warp * 16;

    wmma::fragment<wmma::accumulator, 16, 16, 8, float> acc[4];
#pragma unroll
    for (int mi = 0; mi < 4; mi++) wmma::fill_fragment(acc[mi], 0.f);

#pragma unroll
    for (int tap = 0; tap < 2; tap++) {
        const float* wAt = wA + tap * 64 * WALD;
        int tapOff = PAD + (tap ? offB : offA) + n0;
#pragma unroll
        for (int kf = 0; kf < 4; kf++) {
            wmma::fragment<wmma::matrix_a, 16, 16, 8, wmma::precision::tf32, wmma::row_major> a;
            wmma::fragment<wmma::matrix_b, 16, 16, 8, wmma::precision::tf32, wmma::row_major> bf;
            wmma::load_matrix_sync(bf, &halo[(kf * 8) * HS + tapOff], HS);
#pragma unroll
            for (int mi = 0; mi < 4; mi++) {
                wmma::load_matrix_sync(a, &wAt[(mi * 16) * WALD + kf * 8], WALD);
                wmma::mma_sync(acc[mi], a, bf, acc[mi]);
            }
        }
    }
#pragma unroll
    for (int mi = 0; mi < 2; mi++) {
        float bf0 = bias[mi * 16 + grp];
        float bf1 = bias[mi * 16 + grp + 8];
        float bg0 = bias[32 + mi * 16 + grp];
        float bg1 = bias[32 + mi * 16 + grp + 8];
#pragma unroll
        for (int q = 0; q < 8; q++) {
            float fv = acc[mi].x[q] + (FRAG_HALF(q) ? bf1 : bf0);
            float gv = acc[mi + 2].x[q] + (FRAG_HALF(q) ? bg1 : bg0);
            acc[mi].x[q] = wmma::__float_to_tf32(fv * gv);
        }
        wmma::store_matrix_sync(&u[(mi * 16) * FGLD + n0], acc[mi], FGLD, wmma::mem_row_major);
    }
    __syncwarp();

#pragma unroll
    for (int mi = 0; mi < 4; mi++) wmma::fill_fragment(acc[mi], 0.f);
    {
        const float* wA2 = wA + 2 * 64 * WALD;
#pragma unroll
        for (int kf = 0; kf < 4; kf++) {
            wmma::fragment<wmma::matrix_b, 16, 16, 8, wmma::precision::tf32, wmma::row_major> bf;
            wmma::load_matrix_sync(bf, &u[(kf * 8) * FGLD + n0], FGLD);
#pragma unroll
            for (int mi = 0; mi < 4; mi++) {
                wmma::fragment<wmma::matrix_a, 16, 16, 8, wmma::precision::tf32, wmma::row_major> a;
                wmma::load_matrix_sync(a, &wA2[(mi * 16) * WALD + kf * 8], WALD);
                wmma::mma_sync(acc[mi], a, bf, acc[mi]);
            }
        }
    }
#pragma unroll
    for (int mi = 0; mi < 4; mi++) {
        int base = (mi < 2) ? (64 + mi * 16) : (96 + (mi - 2) * 16);
        float b0 = bias[base + grp];
        float b1 = bias[base + grp + 8];
#pragma unroll
        for (int q = 0; q < 8; q++)
            acc[mi].x[q] += FRAG_HALF(q) ? b1 : b0;
        wmma::store_matrix_sync(&u[(mi * 16) * FGLD + n0], acc[mi], FGLD, wmma::mem_row_major);
    }
    __syncwarp();

    {
        int col4 = n0 + (lane & 3) * 4;
        int cb4 = (lane >> 2) * 4;
#pragma unroll
        for (int cc = 0; cc < 4; cc++) {
            int c = cb4 + cc;
            size_t gidx = (size_t)c * SEQLEN + l0 + col4;
            float4 ur = *(const float4*)&u[c * FGLD + col4];
            float4 us = *(const float4*)&u[(32 + c) * FGLD + col4];
            float4 rv = *(const float4*)&rin[gidx];
            float4 sv = *(const float4*)&sk[gidx];
            rv.x += ur.x; rv.y += ur.y; rv.z += ur.z; rv.w += ur.w;
            sv.x += us.x; sv.y += us.y; sv.z += us.z; sv.w += us.w;
            *(float4*)&rout[gidx] = rv;
            *(float4*)&sk[gidx] = sv;
        }
    }
}

// ----------------------------------------------------------------
// Fused head, HC=64, 256 threads, 2 CTAs/SM.
// 8 warps as 4m x 2n; warp tile M=64 x N=32. W2e staged per-k-step
// (WCHK=8) double-buffered; ~107KB smem.
// ----------------------------------------------------------------
__global__ __launch_bounds__(256, 2)
void k_head(float* __restrict__ out)
{
    extern __shared__ float smem[];
    float* hid  = smem;                       // [264][HLDH]
    float* bsk  = smem + 264 * HLDH;          // [40][HLDH]
    float* wbuf = bsk + 40 * HLDH;            // [2][256][WCLD]

    int tid = threadIdx.x;
    int b = blockIdx.y;
    int l0 = blockIdx.x * HC;

    // B tile: tf32(relu(skip)) rows 0-31, row 32 = 1, rows 33-39 = 0
    for (int i = tid; i < 32 * 16; i += 256) {
        int row = i >> 4, n4 = (i & 15) << 2;
        float4 v = *(const float4*)&g_skip[((size_t)b * RC + row) * SEQLEN + l0 + n4];
        v.x = wmma::__float_to_tf32(v.x > 0.f ? v.x : 0.f);
        v.y = wmma::__float_to_tf32(v.y > 0.f ? v.y : 0.f);
        v.z = wmma::__float_to_tf32(v.z > 0.f ? v.z : 0.f);
        v.w = wmma::__float_to_tf32(v.w > 0.f ? v.w : 0.f);
        *(float4*)&bsk[row * HLDH + n4] = v;
    }
    for (int i = tid; i < 8 * HC; i += 256) {
        int row = 32 + (i >> 6), col = i & 63;
        bsk[row * HLDH + col] = (row == 32) ? 1.f : 0.f;
    }
    for (int i = tid; i < 8 * HC; i += 256) {
        int row = 256 + (i >> 6), col = i & 63;
        hid[row * HLDH + col] = (row == 256) ? 1.f : 0.f;
    }
    __syncthreads();

    int warp = tid >> 5;
    int wm = warp >> 1;             // 0..3 -> rows wm*64..+63
    int wn = warp & 1;              // 0..1 -> cols wn*32..+31
    int m0 = wm * 64;
    int n0 = wn * 32;

    wmma::fragment<wmma::accumulator, 16, 16, 8, float> acc[4][2];

    // ---------------- GEMM1 (K=40, A from L2-hot g_w1e) ----------------
#pragma unroll
    for (int mi = 0; mi < 4; mi++)
#pragma unroll
        for (int ni = 0; ni < 2; ni++) wmma::fill_fragment(acc[mi][ni], 0.f);

#pragma unroll
    for (int kf = 0; kf < 5; kf++) {
        wmma::fragment<wmma::matrix_b, 16, 16, 8, wmma::precision::tf32, wmma::row_major> bf[2];
#pragma unroll
        for (int ni = 0; ni < 2; ni++)
            wmma::load_matrix_sync(bf[ni], &bsk[(kf * 8) * HLDH + n0 + ni * 16], HLDH);
#pragma unroll
        for (int mi = 0; mi < 4; mi++) {
            wmma::fragment<wmma::matrix_a, 16, 16, 8, wmma::precision::tf32, wmma::row_major> a;
            wmma::load_matrix_sync(a, &g_w1e[(m0 + mi * 16) * 40 + kf * 8], 40);
#pragma unroll
            for (int ni = 0; ni < 2; ni++)
                wmma::mma_sync(acc[mi][ni], a, bf[ni], acc[mi][ni]);
        }
    }
#pragma unroll
    for (int mi = 0; mi < 4; mi++)
#pragma unroll
        for (int ni = 0; ni < 2; ni++) {
#pragma unroll
            for (int t = 0; t < acc[mi][ni].num_elements; t++) {
                float v = acc[mi][ni].x[t];
                acc[mi][ni].x[t] = wmma::__float_to_tf32(v > 0.f ? v : 0.f);
            }
            wmma::store_matrix_sync(&hid[(m0 + mi * 16) * HLDH + n0 + ni * 16],
                                    acc[mi][ni], HLDH, wmma::mem_row_major);
        }

    // ---------------- GEMM2: K = 264, 33 chunks of 8 ----------------
#pragma unroll
    for (int mi = 0; mi < 4; mi++)
#pragma unroll
        for (int ni = 0; ni < 2; ni++) wmma::fill_fragment(acc[mi][ni], 0.f);

    // staging: thread t -> row t, 2 float4s (cols 0-3, 4-7)
    // preload chunk 0 into buffer 0 (sync also covers hid stores above)
#pragma unroll
    for (int q = 0; q < 2; q++) {
        float4 v = *(const float4*)&g_w2e[tid * 264 + q * 4];
        *(float4*)&wbuf[tid * WCLD + q * 4] = v;
    }
    __syncthreads();

    for (int c = 0; c < 33; c++) {
        float4 nxt[2];
        if (c < 32) {
#pragma unroll
            for (int q = 0; q < 2; q++)
                nxt[q] = *(const float4*)&g_w2e[tid * 264 + (c + 1) * WCHK + q * 4];
        }

        const float* cur = wbuf + (c & 1) * 256 * WCLD;
        int kk = c * WCHK;
        wmma::fragment<wmma::matrix_b, 16, 16, 8, wmma::precision::tf32, wmma::row_major> bf[2];
#pragma unroll
        for (int ni = 0; ni < 2; ni++)
            wmma::load_matrix_sync(bf[ni], &hid[kk * HLDH + n0 + ni * 16], HLDH);
#pragma unroll
        for (int mi = 0; mi < 4; mi++) {
            wmma::fragment<wmma::matrix_a, 16, 16, 8, wmma::precision::tf32, wmma::row_major> a;
            wmma::load_matrix_sync(a, &cur[(m0 + mi * 16) * WCLD], WCLD);
#pragma unroll
            for (int ni = 0; ni < 2; ni++)
                wmma::mma_sync(acc[mi][ni], a, bf[ni], acc[mi][ni]);
        }

        if (c < 32) {
            float* nbuf = wbuf + ((c + 1) & 1) * 256 * WCLD;
#pragma unroll
            for (int q = 0; q < 2; q++)
                *(float4*)&nbuf[tid * WCLD + q * 4] = nxt[q];
        }
        __syncthreads();
    }

#pragma unroll
    for (int mi = 0; mi < 4; mi++)
#pragma unroll
        for (int ni = 0; ni < 2; ni++) {
            float* dst = &out[((size_t)b * OC + m0 + mi * 16) * SEQLEN + l0 + n0 + ni * 16];
            wmma::store_matrix_sync(dst, acc[mi][ni], SEQLEN, wmma::mem_row_major);
        }
}

// ----------------------------------------------------------------
extern "C" void kernel_launch(void* const* d_in, const int* in_sizes, int n_in,
                              void* d_out, int out_size)
{
    const float* x       = (const float*)d_in[0];
    const float* w_start = (const float*)d_in[1];
    const float* b_start = (const float*)d_in[2];
    const float* filt_w  = (const float*)d_in[3];
    const float* filt_b  = (const float*)d_in[4];
    const float* gate_w  = (const float*)d_in[5];
    const float* gate_b  = (const float*)d_in[6];
    const float* res_w   = (const float*)d_in[7];
    const float* res_b   = (const float*)d_in[8];
    const float* skip_w  = (const float*)d_in[9];
    const float* skip_b  = (const float*)d_in[10];
    const float* w_end1  = (const float*)d_in[11];
    const float* b_end1  = (const float*)d_in[12];
    const float* w_end2  = (const float*)d_in[13];
    const float* b_end2  = (const float*)d_in[14];
    float* out = (float*)d_out;

    static int smem_set = 0;
    if (!smem_set) {
        int tmp = 256 + TL + 256 + 4;
        int hsMax = ((tmp + 3) & ~7) + 4;
        cudaFuncSetAttribute(k_layer_tc, cudaFuncAttributeMaxDynamicSharedMemorySize,
                             (SM_FIXED + 32 * hsMax) * (int)sizeof(float));
        cudaFuncSetAttribute(k_fuse5, cudaFuncAttributeMaxDynamicSharedMemorySize,
                             SM_F5 * (int)sizeof(float));
        cudaFuncSetAttribute(k_head, cudaFuncAttributeMaxDynamicSharedMemorySize,
                             SM_HEAD * (int)sizeof(float));
        smem_set = 1;
    }

    {
        int n = OC * 264 + OC * 40;
        k_prepw<<<(n + 255) / 256, 256>>>(w_end1, b_end1, w_end2, b_end2);
    }

    int ping = 1;
    dim3 gf(SEQLEN / F5TL, BATCH);
    dim3 gl(SEQLEN / TL, BATCH);
    for (int blk = 0; blk < NBLOCKS; blk++) {
        k_fuse5<<<gf, 512, SM_F5 * sizeof(float)>>>(ping, (blk == 0) ? 1 : 0,
            blk * NLAYERS,
            filt_w, filt_b, gate_w, gate_b, res_w, res_b, skip_w, skip_b,
            x, w_start, b_start);
        ping ^= 1;
        for (int i = 5; i < NLAYERS; i++) {
            int li = blk * NLAYERS + i;
            int h = 1 << (i - 1);
            int offA = -h, offB = h;
            int PAD = (h + 3) & ~3;
            int tmp = PAD + TL + offB + 4;
            int HS = ((tmp + 3) & ~7) + 4;
            int smemBytes = (SM_FIXED + 32 * HS) * (int)sizeof(float);
            k_layer_tc<<<gl, 256, smemBytes>>>(ping,
                filt_w + (size_t)li * RC * RC * 2, filt_b + (size_t)li * RC,
                gate_w + (size_t)li * RC * RC * 2, gate_b + (size_t)li * RC,
                res_w  + (size_t)li * RC * RC,     res_b  + (size_t)li * RC,
                skip_w + (size_t)li * RC * RC,     skip_b + (size_t)li * RC,
                offA, offB, PAD, HS);
            ping ^= 1;
        }
    }

    dim3 gh(SEQLEN / HC, BATCH);
    k_head<<<gh, 256, SM_HEAD * sizeof(float)>>>(out);
}

// round 17
// speedup vs baseline: 1.0515x; 1.0515x over previous
#include <cuda_runtime.h>
#include <mma.h>
using namespace nvcuda;

// Problem constants
#define BATCH   4
#define SEQLEN  65536
#define RC      32
#define OC      256
#define NBLOCKS 2
#define NLAYERS 10

#define TL      256           // positions per CTA in k_layer_tc (512 thr)
#define FGLD    260           // staging row stride (covers 256 cols)
#define WALD    40
#define SM_FIXED (64 * FGLD + 3 * 64 * WALD + 128)

// ---- fused-5 kernel geometry ----
#define F5TL    256
#define F5NT    18
#define RS2     316
#define F5LD    292
#define SLD     260
#define SM_F5   (2*32*RS2 + 64*F5LD + 32*SLD + 3*64*WALD + 128)

// ---- head geometry (R15 proven) ----
#define HC      128
#define HLDH    132
#define WCHK    24
#define WCLD    28
#define SM_HEAD (264 * HLDH + 40 * HLDH + 2 * 256 * WCLD)

// -------- scratch (device globals) --------
__device__ float g_resid[2][BATCH * RC * SEQLEN];
__device__ float g_skip[BATCH * RC * SEQLEN];
__device__ float g_w1e[OC * 40];
__device__ float g_w2e[OC * 264];

// ----------------------------------------------------------------
__global__ void k_prepw(const float* __restrict__ w1, const float* __restrict__ b1,
                        const float* __restrict__ w2, const float* __restrict__ b2)
{
    int idx = blockIdx.x * blockDim.x + threadIdx.x;
    const int N2 = OC * 264;
    if (idx < N2) {
        int m = idx / 264, c = idx % 264;
        float v = (c < 256) ? w2[(size_t)m * 256 + c] : (c == 256 ? b2[m] : 0.f);
        g_w2e[idx] = wmma::__float_to_tf32(v);
    } else if (idx < N2 + OC * 40) {
        int j = idx - N2;
        int m = j / 40, c = j % 40;
        float v = (c < 32) ? w1[(size_t)m * 32 + c] : (c == 32 ? b1[m] : 0.f);
        g_w1e[j] = wmma::__float_to_tf32(v);
    }
}

// Fragment row-half selector: element t sits at row (lane>>2) + 8*((t>>1)&1).
#define FRAG_HALF(t) (((t) >> 1) & 1)

// ----------------------------------------------------------------
// Fused first-5 layers of one block (identical to R15).
// ----------------------------------------------------------------
__global__ __launch_bounds__(512, 1)
void k_fuse5(int pingIn, int blk0, int liBase,
             const float* __restrict__ fwB, const float* __restrict__ fbB,
             const float* __restrict__ gwB, const float* __restrict__ gbB,
             const float* __restrict__ rwB, const float* __restrict__ rbB,
             const float* __restrict__ swB, const float* __restrict__ sbB,
             const float* __restrict__ x,
             const float* __restrict__ wst, const float* __restrict__ bst)
{
    extern __shared__ float smem[];
    float* Rb   = smem;
    float* u    = Rb + 2 * 32 * RS2;
    float* S    = u + 64 * F5LD;
    float* wA   = S + 32 * SLD;
    float* bias = wA + 3 * 64 * WALD;

    int tid = threadIdx.x;
    int b = blockIdx.y;
    int l0 = blockIdx.x * F5TL;

    const float* __restrict__ rin = &g_resid[pingIn][(size_t)b * RC * SEQLEN];
    float* __restrict__ rout = &g_resid[pingIn ^ 1][(size_t)b * RC * SEQLEN];
    float* __restrict__ sk = &g_skip[(size_t)b * RC * SEQLEN];

    {
        const float* __restrict__ xb = &x[(size_t)b * SEQLEN];
        for (int i = tid; i < 32 * 72; i += 512) {
            int row = i / 72;
            int col = 16 + (i - row * 72) * 4;
            int l = l0 - 32 + col;
            float4 v = make_float4(0.f, 0.f, 0.f, 0.f);
            if (l >= 0 && l < SEQLEN) {
                if (blk0) {
                    float4 xv = *(const float4*)&xb[l];
                    float wv = wst[row], bv = bst[row];
                    v = make_float4(wv * xv.x + bv, wv * xv.y + bv,
                                    wv * xv.z + bv, wv * xv.w + bv);
                } else {
                    v = *(const float4*)&rin[(size_t)row * SEQLEN + l];
                }
            }
            *(float4*)&Rb[row * RS2 + col] = v;
        }
    }
    for (int i = tid; i < 32 * 64; i += 512) {
        int row = i >> 6;
        int n = (i & 63) * 4;
        float4 v = make_float4(0.f, 0.f, 0.f, 0.f);
        if (!blk0)
            v = *(const float4*)&sk[(size_t)row * SEQLEN + l0 + n];
        *(float4*)&S[row * SLD + n] = v;
    }

    int warp = tid >> 5;
    int lane = tid & 31;
    int grp = lane >> 2;

    int cur = 0;
    for (int j = 0; j < 5; j++) {
        int li = liBase + j;
        int offA, offB;
        if (j == 0) { offA = -1; offB = 0; }
        else { int h = 1 << (j - 1); offA = -h; offB = h; }

        const float2* fw2 = (const float2*)(fwB + (size_t)li * RC * RC * 2);
        const float2* gw2 = (const float2*)(gwB + (size_t)li * RC * RC * 2);
        const float* rw = rwB + (size_t)li * RC * RC;
        const float* sw = swB + (size_t)li * RC * RC;
        for (int i = tid; i < 64 * 32; i += 512) {
            int row = i >> 5, ci = i & 31;
            int c = row & 31;
            float t0, t1, t2;
            if (row < 32) {
                float2 t = fw2[c * 32 + ci];
                t0 = t.x; t1 = t.y; t2 = rw[c * 32 + ci];
            } else {
                float2 t = gw2[c * 32 + ci];
                t0 = t.x; t1 = t.y; t2 = sw[c * 32 + ci];
            }
            wA[0 * 64 * WALD + row * WALD + ci] = wmma::__float_to_tf32(t0);
            wA[1 * 64 * WALD + row * WALD + ci] = wmma::__float_to_tf32(t1);
            wA[2 * 64 * WALD + row * WALD + ci] = wmma::__float_to_tf32(t2);
        }
        if (tid < 32) {
            bias[tid]      = fbB[li * RC + tid];
            bias[32 + tid] = gbB[li * RC + tid];
            bias[64 + tid] = rbB[li * RC + tid];
            bias[96 + tid] = sbB[li * RC + tid];
        }
        __syncthreads();

        const float* Rc = Rb + cur * 32 * RS2;
        float* Rn = Rb + (cur ^ 1) * 32 * RS2;

        for (int tt = 0; tt < 2; tt++) {
            int t = warp + tt * 16;
            if (t >= F5NT) break;
            int n0 = t * 16;

            wmma::fragment<wmma::accumulator, 16, 16, 8, float> acc[4];
#pragma unroll
            for (int mi = 0; mi < 4; mi++) wmma::fill_fragment(acc[mi], 0.f);
#pragma unroll
            for (int tap = 0; tap < 2; tap++) {
                const float* wAt = wA + tap * 64 * WALD;
                int bcol = 16 + n0 + (tap ? offB : offA);
#pragma unroll
                for (int kf = 0; kf < 4; kf++) {
                    wmma::fragment<wmma::matrix_a, 16, 16, 8, wmma::precision::tf32, wmma::row_major> a;
                    wmma::fragment<wmma::matrix_b, 16, 16, 8, wmma::precision::tf32, wmma::row_major> bf;
                    wmma::load_matrix_sync(bf, &Rc[(kf * 8) * RS2 + bcol], RS2);
#pragma unroll
                    for (int q = 0; q < bf.num_elements; q++)
                        bf.x[q] = wmma::__float_to_tf32(bf.x[q]);
#pragma unroll
                    for (int mi = 0; mi < 4; mi++) {
                        wmma::load_matrix_sync(a, &wAt[(mi * 16) * WALD + kf * 8], WALD);
                        wmma::mma_sync(acc[mi], a, bf, acc[mi]);
                    }
                }
            }
#pragma unroll
            for (int mi = 0; mi < 2; mi++) {
                float bf0 = bias[mi * 16 + grp];
                float bf1 = bias[mi * 16 + grp + 8];
                float bg0 = bias[32 + mi * 16 + grp];
                float bg1 = bias[32 + mi * 16 + grp + 8];
#pragma unroll
                for (int q = 0; q < 8; q++) {
                    float fv = acc[mi].x[q] + (FRAG_HALF(q) ? bf1 : bf0);
                    float gv = acc[mi + 2].x[q] + (FRAG_HALF(q) ? bg1 : bg0);
                    acc[mi].x[q] = wmma::__float_to_tf32(fv * gv);
                }
                wmma::store_matrix_sync(&u[(mi * 16) * F5LD + n0], acc[mi], F5LD, wmma::mem_row_major);
            }
            __syncwarp();

#pragma unroll
            for (int mi = 0; mi < 4; mi++) wmma::fill_fragment(acc[mi], 0.f);
            {
                const float* wA2 = wA + 2 * 64 * WALD;
#pragma unroll
                for (int kf = 0; kf < 4; kf++) {
                    wmma::fragment<wmma::matrix_b, 16, 16, 8, wmma::precision::tf32, wmma::row_major> bf;
                    wmma::load_matrix_sync(bf, &u[(kf * 8) * F5LD + n0], F5LD);
#pragma unroll
                    for (int mi = 0; mi < 4; mi++) {
                        wmma::fragment<wmma::matrix_a, 16, 16, 8, wmma::precision::tf32, wmma::row_major> a;
                        wmma::load_matrix_sync(a, &wA2[(mi * 16) * WALD + kf * 8], WALD);
                        wmma::mma_sync(acc[mi], a, bf, acc[mi]);
                    }
                }
            }
#pragma unroll
            for (int mi = 0; mi < 4; mi++) {
                int base = (mi < 2) ? (64 + mi * 16) : (96 + (mi - 2) * 16);
                float b0 = bias[base + grp];
                float b1 = bias[base + grp + 8];
#pragma unroll
                for (int q = 0; q < 8; q++)
                    acc[mi].x[q] += FRAG_HALF(q) ? b1 : b0;
                wmma::store_matrix_sync(&u[(mi * 16) * F5LD + n0], acc[mi], F5LD, wmma::mem_row_major);
            }
            __syncwarp();

            {
                int col4 = n0 + (lane & 3) * 4;
                int cb4 = (lane >> 2) * 4;
                int lb = l0 - 16 + col4;
                bool inS = (col4 >= 16 && col4 < 272);
#pragma unroll
                for (int cc = 0; cc < 4; cc++) {
                    int c = cb4 + cc;
                    float4 ur = *(const float4*)&u[c * F5LD + col4];
                    float4 rc = *(const float4*)&Rc[c * RS2 + 16 + col4];
                    float4 rv;
                    rv.x = (lb + 0 >= 0 && lb + 0 < SEQLEN) ? rc.x + ur.x : 0.f;
                    rv.y = (lb + 1 >= 0 && lb + 1 < SEQLEN) ? rc.y + ur.y : 0.f;
                    rv.z = (lb + 2 >= 0 && lb + 2 < SEQLEN) ? rc.z + ur.z : 0.f;
                    rv.w = (lb + 3 >= 0 && lb + 3 < SEQLEN) ? rc.w + ur.w : 0.f;
                    *(float4*)&Rn[c * RS2 + 16 + col4] = rv;
                    if (inS) {
                        float4 us = *(const float4*)&u[(32 + c) * F5LD + col4];
                        float4 sv = *(const float4*)&S[c * SLD + col4 - 16];
                        sv.x += us.x; sv.y += us.y; sv.z += us.z; sv.w += us.w;
                        *(float4*)&S[c * SLD + col4 - 16] = sv;
                    }
                }
            }
            __syncwarp();
        }
        __syncthreads();
        cur ^= 1;
    }

    const float* Rf = Rb + cur * 32 * RS2;
    for (int i = tid; i < 32 * 64; i += 512) {
        int row = i >> 6;
        int n = (i & 63) * 4;
        *(float4*)&rout[(size_t)row * SEQLEN + l0 + n] = *(const float4*)&Rf[row * RS2 + 32 + n];
        *(float4*)&sk[(size_t)row * SEQLEN + l0 + n] = *(const float4*)&S[row * SLD + n];
    }
}

// ----------------------------------------------------------------
// Single gated dilated layer (dilations >= 16): TL=256, 512 threads,
// 16 warps x 16-col slices. Same pipeline as R15 otherwise.
// ----------------------------------------------------------------
__global__ __launch_bounds__(512, 1)
void k_layer_tc(int ping,
                const float* __restrict__ fw, const float* __restrict__ fb,
                const float* __restrict__ gw, const float* __restrict__ gb,
                const float* __restrict__ rw, const float* __restrict__ rb,
                const float* __restrict__ sw, const float* __restrict__ sb,
                int offA, int offB, int PAD, int HS)
{
    extern __shared__ float smem[];
    float* halo = smem;
    float* u    = smem + 32 * HS;
    float* wA   = u + 64 * FGLD;
    float* bias = wA + 3 * 64 * WALD;

    int tid = threadIdx.x;
    int b = blockIdx.y;
    int l0 = blockIdx.x * TL;

    const float* __restrict__ rin = &g_resid[ping][(size_t)b * RC * SEQLEN];
    float* __restrict__ rout = &g_resid[ping ^ 1][(size_t)b * RC * SEQLEN];
    float* __restrict__ sk = &g_skip[(size_t)b * RC * SEQLEN];

    const float2* fw2 = (const float2*)fw;
    const float2* gw2 = (const float2*)gw;
    for (int i = tid; i < 64 * 32; i += 512) {
        int row = i >> 5, ci = i & 31;
        int c = row & 31;
        float t0, t1, t2;
        if (row < 32) {
            float2 t = fw2[c * 32 + ci];
            t0 = t.x; t1 = t.y; t2 = rw[c * 32 + ci];
        } else {
            float2 t = gw2[c * 32 + ci];
            t0 = t.x; t1 = t.y; t2 = sw[c * 32 + ci];
        }
        wA[0 * 64 * WALD + row * WALD + ci] = wmma::__float_to_tf32(t0);
        wA[1 * 64 * WALD + row * WALD + ci] = wmma::__float_to_tf32(t1);
        wA[2 * 64 * WALD + row * WALD + ci] = wmma::__float_to_tf32(t2);
    }
    if (tid < 32) {
        bias[tid]      = fb[tid];
        bias[32 + tid] = gb[tid];
        bias[64 + tid] = rb[tid];
        bias[96 + tid] = sb[tid];
    }

    {
        int c0 = (PAD + offA) & ~3;
        int c1 = (PAD + TL + offB + 4) & ~3;
        int w4 = (c1 - c0) >> 2;
        for (int i = tid; i < 32 * w4; i += 512) {
            int row = i / w4;
            int col = c0 + ((i - row * w4) << 2);
            int l = l0 - PAD + col;
            float4 v = make_float4(0.f, 0.f, 0.f, 0.f);
            if (l >= 0 && l < SEQLEN)
                v = *(const float4*)&rin[(size_t)row * SEQLEN + l];
            v.x = wmma::__float_to_tf32(v.x);
            v.y = wmma::__float_to_tf32(v.y);
            v.z = wmma::__float_to_tf32(v.z);
            v.w = wmma::__float_to_tf32(v.w);
            *(float4*)&halo[row * HS + col] = v;
        }
    }
    __syncthreads();

    int warp = tid >> 5;          // 0..15
    int lane = tid & 31;
    int grp = lane >> 2;
    int n0 = warp * 16;

    wmma::fragment<wmma::accumulator, 16, 16, 8, float> acc[4];
#pragma unroll
    for (int mi = 0; mi < 4; mi++) wmma::fill_fragment(acc[mi], 0.f);

#pragma unroll
    for (int tap = 0; tap < 2; tap++) {
        const float* wAt = wA + tap * 64 * WALD;
        int tapOff = PAD + (tap ? offB : offA) + n0;
#pragma unroll
        for (int kf = 0; kf < 4; kf++) {
            wmma::fragment<wmma::matrix_a, 16, 16, 8, wmma::precision::tf32, wmma::row_major> a;
            wmma::fragment<wmma::matrix_b, 16, 16, 8, wmma::precision::tf32, wmma::row_major> bf;
            wmma::load_matrix_sync(bf, &halo[(kf * 8) * HS + tapOff], HS);
#pragma unroll
            for (int mi = 0; mi < 4; mi++) {
                wmma::load_matrix_sync(a, &wAt[(mi * 16) * WALD + kf * 8], WALD);
                wmma::mma_sync(acc[mi], a, bf, acc[mi]);
            }
        }
    }
#pragma unroll
    for (int mi = 0; mi < 2; mi++) {
        float bf0 = bias[mi * 16 + grp];
        float bf1 = bias[mi * 16 + grp + 8];
        float bg0 = bias[32 + mi * 16 + grp];
        float bg1 = bias[32 + mi * 16 + grp + 8];
#pragma unroll
        for (int q = 0; q < 8; q++) {
            float fv = acc[mi].x[q] + (FRAG_HALF(q) ? bf1 : bf0);
            float gv = acc[mi + 2].x[q] + (FRAG_HALF(q) ? bg1 : bg0);
            acc[mi].x[q] = wmma::__float_to_tf32(fv * gv);
        }
        wmma::store_matrix_sync(&u[(mi * 16) * FGLD + n0], acc[mi], FGLD, wmma::mem_row_major);
    }
    __syncwarp();

#pragma unroll
    for (int mi = 0; mi < 4; mi++) wmma::fill_fragment(acc[mi], 0.f);
    {
        const float* wA2 = wA + 2 * 64 * WALD;
#pragma unroll
        for (int kf = 0; kf < 4; kf++) {
            wmma::fragment<wmma::matrix_b, 16, 16, 8, wmma::precision::tf32, wmma::row_major> bf;
            wmma::load_matrix_sync(bf, &u[(kf * 8) * FGLD + n0], FGLD);
#pragma unroll
            for (int mi = 0; mi < 4; mi++) {
                wmma::fragment<wmma::matrix_a, 16, 16, 8, wmma::precision::tf32, wmma::row_major> a;
                wmma::load_matrix_sync(a, &wA2[(mi * 16) * WALD + kf * 8], WALD);
                wmma::mma_sync(acc[mi], a, bf, acc[mi]);
            }
        }
    }
#pragma unroll
    for (int mi = 0; mi < 4; mi++) {
        int base = (mi < 2) ? (64 + mi * 16) : (96 + (mi - 2) * 16);
        float b0 = bias[base + grp];
        float b1 = bias[base + grp + 8];
#pragma unroll
        for (int q = 0; q < 8; q++)
            acc[mi].x[q] += FRAG_HALF(q) ? b1 : b0;
        wmma::store_matrix_sync(&u[(mi * 16) * FGLD + n0], acc[mi], FGLD, wmma::mem_row_major);
    }
    __syncwarp();

    {
        int col4 = n0 + (lane & 3) * 4;
        int cb4 = (lane >> 2) * 4;
#pragma unroll
        for (int cc = 0; cc < 4; cc++) {
            int c = cb4 + cc;
            size_t gidx = (size_t)c * SEQLEN + l0 + col4;
            float4 ur = *(const float4*)&u[c * FGLD + col4];
            float4 us = *(const float4*)&u[(32 + c) * FGLD + col4];
            float4 rv = *(const float4*)&rin[gidx];
            float4 sv = *(const float4*)&sk[gidx];
            rv.x += ur.x; rv.y += ur.y; rv.z += ur.z; rv.w += ur.w;
            sv.x += us.x; sv.y += us.y; sv.z += us.z; sv.w += us.w;
            *(float4*)&rout[gidx] = rv;
            *(float4*)&sk[gidx] = sv;
        }
    }
}

// ----------------------------------------------------------------
// Fused head (R15 config: HC=128, 512 threads, WCHK=24).
// ----------------------------------------------------------------
__global__ __launch_bounds__(512, 1)
void k_head(float* __restrict__ out)
{
    extern __shared__ float smem[];
    float* hid  = smem;
    float* bsk  = smem + 264 * HLDH;
    float* wbuf = bsk + 40 * HLDH;

    int tid = threadIdx.x;
    int b = blockIdx.y;
    int l0 = blockIdx.x * HC;

    for (int i = tid; i < 32 * 32; i += 512) {
        int row = i >> 5, n4 = (i & 31) << 2;
        float4 v = *(const float4*)&g_skip[((size_t)b * RC + row) * SEQLEN + l0 + n4];
        v.x = wmma::__float_to_tf32(v.x > 0.f ? v.x : 0.f);
        v.y = wmma::__float_to_tf32(v.y > 0.f ? v.y : 0.f);
        v.z = wmma::__float_to_tf32(v.z > 0.f ? v.z : 0.f);
        v.w = wmma::__float_to_tf32(v.w > 0.f ? v.w : 0.f);
        *(float4*)&bsk[row * HLDH + n4] = v;
    }
    for (int i = tid; i < 8 * HC; i += 512) {
        int row = 32 + (i >> 7), col = i & 127;
        bsk[row * HLDH + col] = (row == 32) ? 1.f : 0.f;
    }
    for (int i = tid; i < 8 * HC; i += 512) {
        int row = 256 + (i >> 7), col = i & 127;
        hid[row * HLDH + col] = (row == 256) ? 1.f : 0.f;
    }
    __syncthreads();

    int warp = tid >> 5;
    int wm = warp >> 2;
    int wn = warp & 3;
    int m0 = wm * 64;
    int n0 = wn * 32;

    wmma::fragment<wmma::accumulator, 16, 16, 8, float> acc[4][2];

#pragma unroll
    for (int mi = 0; mi < 4; mi++)
#pragma unroll
        for (int ni = 0; ni < 2; ni++) wmma::fill_fragment(acc[mi][ni], 0.f);

#pragma unroll
    for (int kf = 0; kf < 5; kf++) {
        wmma::fragment<wmma::matrix_b, 16, 16, 8, wmma::precision::tf32, wmma::row_major> bf[2];
#pragma unroll
        for (int ni = 0; ni < 2; ni++)
            wmma::load_matrix_sync(bf[ni], &bsk[(kf * 8) * HLDH + n0 + ni * 16], HLDH);
#pragma unroll
        for (int mi = 0; mi < 4; mi++) {
            wmma::fragment<wmma::matrix_a, 16, 16, 8, wmma::precision::tf32, wmma::row_major> a;
            wmma::load_matrix_sync(a, &g_w1e[(m0 + mi * 16) * 40 + kf * 8], 40);
#pragma unroll
            for (int ni = 0; ni < 2; ni++)
                wmma::mma_sync(acc[mi][ni], a, bf[ni], acc[mi][ni]);
        }
    }
#pragma unroll
    for (int mi = 0; mi < 4; mi++)
#pragma unroll
        for (int ni = 0; ni < 2; ni++) {
#pragma unroll
            for (int t = 0; t < acc[mi][ni].num_elements; t++) {
                float v = acc[mi][ni].x[t];
                acc[mi][ni].x[t] = wmma::__float_to_tf32(v > 0.f ? v : 0.f);
            }
            wmma::store_matrix_sync(&hid[(m0 + mi * 16) * HLDH + n0 + ni * 16],
                                    acc[mi][ni], HLDH, wmma::mem_row_major);
        }

#pragma unroll
    for (int mi = 0; mi < 4; mi++)
#pragma unroll
        for (int ni = 0; ni < 2; ni++) wmma::fill_fragment(acc[mi][ni], 0.f);

    int srow = tid >> 1;
    int scol = (tid & 1) * 12;
#pragma unroll
    for (int q = 0; q < 3; q++) {
        float4 v = *(const float4*)&g_w2e[srow * 264 + scol + q * 4];
        *(float4*)&wbuf[srow * WCLD + scol + q * 4] = v;
    }
    __syncthreads();

    for (int c = 0; c < 11; c++) {
        float4 nxt[3];
        if (c < 10) {
#pragma unroll
            for (int q = 0; q < 3; q++)
                nxt[q] = *(const float4*)&g_w2e[srow * 264 + (c + 1) * WCHK + scol + q * 4];
        }

        const float* cur = wbuf + (c & 1) * 256 * WCLD;
#pragma unroll
        for (int j = 0; j < 3; j++) {
            int kk = c * WCHK + j * 8;
            wmma::fragment<wmma::matrix_b, 16, 16, 8, wmma::precision::tf32, wmma::row_major> bf[2];
#pragma unroll
            for (int ni = 0; ni < 2; ni++)
                wmma::load_matrix_sync(bf[ni], &hid[kk * HLDH + n0 + ni * 16], HLDH);
#pragma unroll
            for (int mi = 0; mi < 4; mi++) {
                wmma::fragment<wmma::matrix_a, 16, 16, 8, wmma::precision::tf32, wmma::row_major> a;
                wmma::load_matrix_sync(a, &cur[(m0 + mi * 16) * WCLD + j * 8], WCLD);
#pragma unroll
                for (int ni = 0; ni < 2; ni++)
                    wmma::mma_sync(acc[mi][ni], a, bf[ni], acc[mi][ni]);
            }
        }

        if (c < 10) {
            float* nbuf = wbuf + ((c + 1) & 1) * 256 * WCLD;
#pragma unroll
            for (int q = 0; q < 3; q++)
                *(float4*)&nbuf[srow * WCLD + scol + q * 4] = nxt[q];
        }
        __syncthreads();
    }

#pragma unroll
    for (int mi = 0; mi < 4; mi++)
#pragma unroll
        for (int ni = 0; ni < 2; ni++) {
            float* dst = &out[((size_t)b * OC + m0 + mi * 16) * SEQLEN + l0 + n0 + ni * 16];
            wmma::store_matrix_sync(dst, acc[mi][ni], SEQLEN, wmma::mem_row_major);
        }
}

// ----------------------------------------------------------------
extern "C" void kernel_launch(void* const* d_in, const int* in_sizes, int n_in,
                              void* d_out, int out_size)
{
    const float* x       = (const float*)d_in[0];
    const float* w_start = (const float*)d_in[1];
    const float* b_start = (const float*)d_in[2];
    const float* filt_w  = (const float*)d_in[3];
    const float* filt_b  = (const float*)d_in[4];
    const float* gate_w  = (const float*)d_in[5];
    const float* gate_b  = (const float*)d_in[6];
    const float* res_w   = (const float*)d_in[7];
    const float* res_b   = (const float*)d_in[8];
    const float* skip_w  = (const float*)d_in[9];
    const float* skip_b  = (const float*)d_in[10];
    const float* w_end1  = (const float*)d_in[11];
    const float* b_end1  = (const float*)d_in[12];
    const float* w_end2  = (const float*)d_in[13];
    const float* b_end2  = (const float*)d_in[14];
    float* out = (float*)d_out;

    static int smem_set = 0;
    if (!smem_set) {
        int tmp = 256 + TL + 256 + 4;          // max at h=256
        int hsMax = ((tmp + 3) & ~7) + 4;
        cudaFuncSetAttribute(k_layer_tc, cudaFuncAttributeMaxDynamicSharedMemorySize,
                             (SM_FIXED + 32 * hsMax) * (int)sizeof(float));
        cudaFuncSetAttribute(k_fuse5, cudaFuncAttributeMaxDynamicSharedMemorySize,
                             SM_F5 * (int)sizeof(float));
        cudaFuncSetAttribute(k_head, cudaFuncAttributeMaxDynamicSharedMemorySize,
                             SM_HEAD * (int)sizeof(float));
        smem_set = 1;
    }

    {
        int n = OC * 264 + OC * 40;
        k_prepw<<<(n + 255) / 256, 256>>>(w_end1, b_end1, w_end2, b_end2);
    }

    int ping = 1;
    dim3 gf(SEQLEN / F5TL, BATCH);
    dim3 gl(SEQLEN / TL, BATCH);
    for (int blk = 0; blk < NBLOCKS; blk++) {
        k_fuse5<<<gf, 512, SM_F5 * sizeof(float)>>>(ping, (blk == 0) ? 1 : 0,
            blk * NLAYERS,
            filt_w, filt_b, gate_w, gate_b, res_w, res_b, skip_w, skip_b,
            x, w_start, b_start);
        ping ^= 1;
        for (int i = 5; i < NLAYERS; i++) {
            int li = blk * NLAYERS + i;
            int h = 1 << (i - 1);
            int offA = -h, offB = h;
            int PAD = (h + 3) & ~3;
            int tmp = PAD + TL + offB + 4;
            int HS = ((tmp + 3) & ~7) + 4;
            int smemBytes = (SM_FIXED + 32 * HS) * (int)sizeof(float);
            k_layer_tc<<<gl, 512, smemBytes>>>(ping,
                filt_w + (size_t)li * RC * RC * 2, filt_b + (size_t)li * RC,
                gate_w + (size_t)li * RC * RC * 2, gate_b + (size_t)li * RC,
                res_w  + (size_t)li * RC * RC,     res_b  + (size_t)li * RC,
                skip_w + (size_t)li * RC * RC,     skip_b + (size_t)li * RC,
                offA, offB, PAD, HS);
            ping ^= 1;
        }
    }

    dim3 gh(SEQLEN / HC, BATCH);
    k_head<<<gh, 512, SM_HEAD * sizeof(float)>>>(out);
}